// round 1
// baseline (speedup 1.0000x reference)
#include <cuda_runtime.h>

// Problem constants (shapes fixed by the dataset)
#define NS      32768   // n_series
#define NT      512     // n_time
#define NSTEPS  511
#define SEASK   24
#define LEVW    512     // levels row width
#define SEAW    536     // seasonalities row width (24 + 1 + 511)
#define LOGW    511     // log_diff row width

#define BLOCK   128
#define CHUNK   16      // time steps per staged chunk
#define NCHUNK  (NT / CHUNK)   // 32
#define TPAD    (CHUNK + 1)    // smem row pad to kill bank conflicts

__global__ __launch_bounds__(BLOCK) void es_fwd_kernel(
    const float* __restrict__ y,          // [NS, NT]
    const int*   __restrict__ idxs,       // [NS]
    const float* __restrict__ lev_sms_p,  // [MAX, 1]
    const float* __restrict__ init_seas_p,// [MAX, 24]
    float* __restrict__ out)              // levels | seasonalities | log_diff
{
    // Seasonal state: buf[pos][tid] -> bank = tid%32, conflict-free
    __shared__ float buf[SEASK * BLOCK];            // 12.3 KB
    __shared__ float ytile[BLOCK * TPAD];           // y in, log_diff out (reused)
    __shared__ float ltile[BLOCK * TPAD];           // levels staging
    __shared__ float stile[BLOCK * TPAD];           // seasonalities staging

    const int tid = threadIdx.x;
    const int s0  = blockIdx.x * BLOCK;             // first series of this block
    const int s   = s0 + tid;

    float* gl = out;                                // levels  [NS][512]
    float* gs = out + (size_t)NS * LEVW;            // seas    [NS][536]
    float* gd = gs  + (size_t)NS * SEAW;            // logdiff [NS][511]

    const int idx = idxs[s];
    // NOTE: reference computes BOTH smoothing params from lev_sms_p (its own quirk).
    const float a   = 1.0f / (1.0f + __expf(-lev_sms_p[idx]));
    const float oma = 1.0f - a;

    // ---- init seasonal buffer = exp(init_seas[idx,:]); also emit seas[0..23] ----
    {
        const float4* isr = (const float4*)(init_seas_p + (size_t)idx * SEASK); // 96B rows, 16B aligned
        float4* gsr = (float4*)(gs + (size_t)s * SEAW);                          // row stride 2144B, 16B aligned
        #pragma unroll
        for (int q = 0; q < 6; q++) {
            float4 v = isr[q];
            v.x = __expf(v.x); v.y = __expf(v.y); v.z = __expf(v.z); v.w = __expf(v.w);
            buf[(q * 4 + 0) * BLOCK + tid] = v.x;
            buf[(q * 4 + 1) * BLOCK + tid] = v.y;
            buf[(q * 4 + 2) * BLOCK + tid] = v.z;
            buf[(q * 4 + 3) * BLOCK + tid] = v.w;
            gsr[q] = v;
        }
    }

    float lev  = 0.0f;   // level carry
    float llev = 0.0f;   // log(level) carry

    for (int c = 0; c < NCHUNK; c++) {
        const int t0 = c * CHUNK;

        // ---- cooperative coalesced load: ytile[r][k] = y[s0+r][t0+k] ----
        __syncthreads();   // tiles free (prev writeback done)
        #pragma unroll
        for (int i = tid; i < BLOCK * CHUNK; i += BLOCK) {
            const int r = i >> 4;          // CHUNK = 16
            const int k = i & 15;
            ytile[r * TPAD + k] = y[(size_t)(s0 + r) * NT + t0 + k];
        }
        __syncthreads();

        int kstart = 0;
        if (c == 0) {
            // t = 0: lev0 = y[s][0] / exp(init_seas[idx][0])
            const float is0 = buf[tid];                  // pos 0 column
            const float y0  = ytile[tid * TPAD + 0];
            lev  = __fdividef(y0, is0);
            llev = __logf(lev);
            ltile[tid * TPAD + 0] = lev;                 // levels[s][0]
            stile[tid * TPAD + 0] = is0;                 // seas[s][24] = init_seas[:,0]
            // ytile slot 0 (log_diff j = -1) is skipped in writeback
            kstart = 1;
        }

        // pos for step t = t0 + k is (t0 + k) % 24
        int pos = t0 % SEASK;
        pos += kstart; if (pos >= SEASK) pos -= SEASK;

        #pragma unroll
        for (int k = kstart; k < CHUNK; k++) {
            const float yt = ytile[tid * TPAD + k];
            const float st = buf[pos * BLOCK + tid];
            const float nl = fmaf(a, __fdividef(yt, st), oma * lev);   // new level
            const float ns = fmaf(a, __fdividef(yt, nl), oma * st);    // new season
            const float ll = __logf(nl);
            buf[pos * BLOCK + tid]  = ns;
            ytile[tid * TPAD + k]   = ll - llev;   // log_diff at j = t-1
            ltile[tid * TPAD + k]   = nl;
            stile[tid * TPAD + k]   = ns;
            lev = nl; llev = ll;
            pos++; if (pos >= SEASK) pos -= SEASK;
        }
        __syncthreads();

        // ---- cooperative coalesced writeback of all three streams ----
        #pragma unroll
        for (int i = tid; i < BLOCK * CHUNK; i += BLOCK) {
            const int r = i >> 4;
            const int k = i & 15;
            const int grow = s0 + r;
            const float lv = ltile[r * TPAD + k];
            const float sv = stile[r * TPAD + k];
            const float dv = ytile[r * TPAD + k];
            gl[(size_t)grow * LEVW + t0 + k]       = lv;             // levels[grow][t]
            gs[(size_t)grow * SEAW + t0 + k + 24]  = sv;             // seas[grow][t+24]
            const int j = t0 + k - 1;                                // log_diff index
            if (j >= 0) gd[(size_t)grow * LOGW + j] = dv;
        }
    }
}

extern "C" void kernel_launch(void* const* d_in, const int* in_sizes, int n_in,
                              void* d_out, int out_size)
{
    // metadata order: y, idxs, lev_sms, seas_sms, init_seas, seasonality, output_size
    const float* y         = (const float*)d_in[0];
    const int*   idxs      = (const int*)  d_in[1];
    const float* lev_sms   = (const float*)d_in[2];
    // d_in[3] (seas_sms) intentionally unused — reference derives both params from lev_sms
    const float* init_seas = (const float*)d_in[4];
    float* out = (float*)d_out;

    es_fwd_kernel<<<NS / BLOCK, BLOCK>>>(y, idxs, lev_sms, init_seas, out);
}

// round 2
// speedup vs baseline: 1.2121x; 1.2121x over previous
#include <cuda_runtime.h>

#define NS      32768
#define NT      512
#define SEASK   24
#define LEVW    512
#define SEAW    536
#define LOGW    511

#define BLOCK   32
#define CHUNK   16
#define NCHUNK  (NT / CHUNK)    // 32
#define TPAD    (CHUNK + 1)     // 17, odd -> conflict-free strided access

// Process one 16-step chunk. All seasonal-buffer reads within a chunk refer to
// slots written >= 24 steps earlier (CHUNK < SEASK), so reads hoist above writes.
// KSTART=1 for chunk 0 (step 0 handled specially by caller).
template<int KSTART>
__device__ __forceinline__ void chunk_body(
    const float* __restrict__ ysm,   // &ytile[cur][tid*TPAD]
    float* __restrict__ buf,         // seasonal state [24][BLOCK]
    float* __restrict__ lt,          // &ltile[tid*TPAD]
    float* __restrict__ st_t,        // &stile[tid*TPAD]
    float* __restrict__ dt,          // &dtile[tid*TPAD]
    int tid, int pos0, float a, float oma,
    float& lev, float& llev)
{
    float yt[CHUNK], q[CHUNK], os[CHUNK], nl[CHUNK];

    // independent: loads + first divide (RCP pipeline)
    #pragma unroll
    for (int k = KSTART; k < CHUNK; k++) {
        int p = pos0 + k; if (p >= SEASK) p -= SEASK;
        const float sv = buf[p * BLOCK + tid];
        yt[k] = ysm[k];
        q[k]  = a * __fdividef(yt[k], sv);
        os[k] = oma * sv;
    }
    // serial carried chain: one FFMA per step
    #pragma unroll
    for (int k = KSTART; k < CHUNK; k++) {
        nl[k] = fmaf(oma, lev, q[k]);
        lev = nl[k];
    }
    // independent: season update (second RCP pipeline) + buf/tile writes
    #pragma unroll
    for (int k = KSTART; k < CHUNK; k++) {
        const float ns = fmaf(a, __fdividef(yt[k], nl[k]), os[k]);
        int p = pos0 + k; if (p >= SEASK) p -= SEASK;
        buf[p * BLOCK + tid] = ns;
        st_t[k] = ns;
        lt[k]   = nl[k];
    }
    // logs independent; diff chain is cheap FADDs
    #pragma unroll
    for (int k = KSTART; k < CHUNK; k++) {
        const float ll = __logf(nl[k]);
        dt[k] = ll - llev;
        llev = ll;
    }
}

__global__ __launch_bounds__(BLOCK) void es_fwd_kernel(
    const float* __restrict__ y,
    const int*   __restrict__ idxs,
    const float* __restrict__ lev_sms_p,
    const float* __restrict__ init_seas_p,
    float* __restrict__ out)
{
    __shared__ float buf[SEASK * BLOCK];        // seasonal state
    __shared__ float ytile[2][BLOCK * TPAD];    // double-buffered y staging
    __shared__ float ltile[BLOCK * TPAD];
    __shared__ float stile[BLOCK * TPAD];
    __shared__ float dtile[BLOCK * TPAD];

    const int tid = threadIdx.x;
    const int s0  = blockIdx.x * BLOCK;
    const int s   = s0 + tid;

    float* gl = out;
    float* gs = out + (size_t)NS * LEVW;
    float* gd = gs  + (size_t)NS * SEAW;

    const int idx = idxs[s];
    // reference derives BOTH smoothing params from lev_sms (its own quirk)
    const float a   = 1.0f / (1.0f + __expf(-lev_sms_p[idx]));
    const float oma = 1.0f - a;

    // seasonal buffer init + emit seas[0..23]
    {
        const float4* isr = (const float4*)(init_seas_p + (size_t)idx * SEASK);
        float4* gsr = (float4*)(gs + (size_t)s * SEAW);
        #pragma unroll
        for (int qd = 0; qd < 6; qd++) {
            float4 v = isr[qd];
            v.x = __expf(v.x); v.y = __expf(v.y); v.z = __expf(v.z); v.w = __expf(v.w);
            buf[(qd * 4 + 0) * BLOCK + tid] = v.x;
            buf[(qd * 4 + 1) * BLOCK + tid] = v.y;
            buf[(qd * 4 + 2) * BLOCK + tid] = v.z;
            buf[(qd * 4 + 3) * BLOCK + tid] = v.w;
            gsr[qd] = v;
        }
    }

    // preload chunk 0 (coalesced cooperative)
    #pragma unroll
    for (int j = 0; j < CHUNK; j++) {
        const int i = tid + j * BLOCK;
        const int r = i >> 4, k = i & 15;
        ytile[0][r * TPAD + k] = y[(size_t)(s0 + r) * NT + k];
    }
    __syncwarp();

    float lev = 0.0f, llev = 0.0f;
    int pos0 = 0;

    float* lt   = &ltile[tid * TPAD];
    float* st_t = &stile[tid * TPAD];
    float* dt   = &dtile[tid * TPAD];

    #pragma unroll 1
    for (int c = 0; c < NCHUNK; c++) {
        const int cur = c & 1, nxt = cur ^ 1;
        const int t0 = c * CHUNK;

        // issue LDGs for next chunk early (latency hidden under compute)
        float pre[CHUNK];
        if (c + 1 < NCHUNK) {
            #pragma unroll
            for (int j = 0; j < CHUNK; j++) {
                const int i = tid + j * BLOCK;
                const int r = i >> 4, k = i & 15;
                pre[j] = y[(size_t)(s0 + r) * NT + (t0 + CHUNK) + k];
            }
        }

        const float* ysm = &ytile[cur][tid * TPAD];

        if (c == 0) {
            // step 0: lev0 = y0 / exp(init_seas[:,0])
            const float st0 = buf[tid];          // pos 0
            const float y0  = ysm[0];
            lev  = __fdividef(y0, st0);
            llev = __logf(lev);
            lt[0]   = lev;
            st_t[0] = st0;                       // seas col 24 = init_seas[:,0]
            dt[0]   = 0.0f;                      // never written (j = -1)
            chunk_body<1>(ysm, buf, lt, st_t, dt, tid, pos0, a, oma, lev, llev);
        } else {
            chunk_body<0>(ysm, buf, lt, st_t, dt, tid, pos0, a, oma, lev, llev);
        }
        pos0 += CHUNK; if (pos0 >= SEASK) pos0 -= SEASK;

        __syncwarp();

        // stage next chunk into the other buffer
        if (c + 1 < NCHUNK) {
            #pragma unroll
            for (int j = 0; j < CHUNK; j++) {
                const int i = tid + j * BLOCK;
                const int r = i >> 4, k = i & 15;
                ytile[nxt][r * TPAD + k] = pre[j];
            }
        }

        // coalesced writeback of all three streams
        #pragma unroll
        for (int j = 0; j < CHUNK; j++) {
            const int i = tid + j * BLOCK;
            const int r = i >> 4, k = i & 15;
            const int grow = s0 + r;
            gl[(size_t)grow * LEVW + t0 + k]      = ltile[r * TPAD + k];
            gs[(size_t)grow * SEAW + t0 + k + 24] = stile[r * TPAD + k];
            const int jj = t0 + k - 1;
            if (jj >= 0) gd[(size_t)grow * LOGW + jj] = dtile[r * TPAD + k];
        }
        __syncwarp();
    }
}

extern "C" void kernel_launch(void* const* d_in, const int* in_sizes, int n_in,
                              void* d_out, int out_size)
{
    const float* y         = (const float*)d_in[0];
    const int*   idxs      = (const int*)  d_in[1];
    const float* lev_sms   = (const float*)d_in[2];
    const float* init_seas = (const float*)d_in[4];  // d_in[3] unused (reference quirk)
    float* out = (float*)d_out;

    es_fwd_kernel<<<NS / BLOCK, BLOCK>>>(y, idxs, lev_sms, init_seas, out);
}